// round 4
// baseline (speedup 1.0000x reference)
#include <cuda_runtime.h>
#include <cuda_bf16.h>
#include <cstdint>

#define BB   2
#define KK   32
#define CC   256
#define IHW  512
#define OHW  16
#define NCH  (3 + CC)
#define NPIX (OHW * OHW)

#define MAXSPAN 40          // window span bound (analysis: <= ~36)
#define SSTRIDE 41          // odd stride -> conflict-free banks
#define CHB     2           // channels per staged batch
#define NBATCH  (16 / CHB)  // 8 batches per group

__global__ __launch_bounds__(256, 6)
void roialign_kernel(const float* __restrict__ imgs,
                     const float* __restrict__ bboxess,
                     const int*   __restrict__ counts,
                     const float* __restrict__ p2,
                     const float* __restrict__ p3,
                     const float* __restrict__ p4,
                     const float* __restrict__ p5,
                     float*       __restrict__ out)
{
    const int bk  = blockIdx.x;          // 0..B*K-1
    const int b   = bk / KK;
    const int k   = bk % KK;
    const int grp = blockIdx.y;          // 0 = image channels, 1..16 = feature groups
    const int tid = threadIdx.x;         // one output pixel
    const int oy  = tid >> 4;
    const int ox  = tid & 15;

    float* outBox = out + (size_t)bk * NCH * NPIX;

    const bool valid = (k < __ldg(counts + b));
    if (!valid) {
        if (grp == 0) {
            #pragma unroll
            for (int c = 0; c < 3; ++c) outBox[c * NPIX + tid] = 0.0f;
        } else {
            const int c0 = 3 + (grp - 1) * 16;
            #pragma unroll
            for (int cc = 0; cc < 16; ++cc) outBox[(c0 + cc) * NPIX + tid] = 0.0f;
        }
        return;
    }

    // ---- per-box scalars ----
    const float by1 = __ldg(bboxess + bk * 4 + 0);
    const float bx1 = __ldg(bboxess + bk * 4 + 1);
    const float by2 = __ldg(bboxess + bk * 4 + 2);
    const float bx2 = __ldg(bboxess + bk * 4 + 3);

    const float area = (by2 - by1) * (bx2 - bx1);
    float lx = 6.0f + 0.5f * log2f(area * (1.0f / ((float)IHW * (float)IHW)));
    lx = fminf(fmaxf(lx, 2.0f), 5.0f);
    const int lvl = (int)rintf(lx);
    const int ph  = IHW >> lvl;
    const float scale = (float)ph / (float)IHW;

    int y1i = min(max((int)rintf(by1), 0), IHW - 1);
    int x1i = min(max((int)rintf(bx1), 0), IHW - 1);
    int y2i = min(max((int)rintf(by2), y1i + 1), IHW);
    int x2i = min(max((int)rintf(bx2), x1i + 1), IHW);

    // ---- tap tables ----
    __shared__ int   sRowIdx[OHW][4];
    __shared__ float sRowW[OHW][4];
    __shared__ int   sColIdx[OHW][4];
    __shared__ float sColW[OHW][4];
    __shared__ int   sImgY[OHW][2];
    __shared__ float sImgWY[OHW][2];
    __shared__ int   sImgX[OHW][2];
    __shared__ float sImgWX[OHW][2];
    __shared__ int   sRowLo, sRowHi, sColLo, sColHi;
    __shared__ float sWin[2][CHB][MAXSPAN * SSTRIDE];   // ping-pong, 26.2 KB

    if (tid < 16) {
        const int o = tid;
        const float sf = (float)(y2i - y1i);
        const float s  = fmaxf(((float)o + 0.5f) * sf / (float)OHW - 0.5f, 0.0f);
        const int   j0 = (int)floorf(s);
        const int   j1 = min(j0 + 1, (y2i - y1i) - 1);
        const float wt = s - (float)j0;
        const int yi[2]  = { y1i + j0, y1i + j1 };
        const float W[2] = { 1.0f - wt, wt };
        #pragma unroll
        for (int a = 0; a < 2; ++a) {
            sImgY[o][a]  = yi[a];
            sImgWY[o][a] = W[a];
            const float sy = fmaxf(((float)yi[a] + 0.5f) * scale - 0.5f, 0.0f);
            const int   q0 = (int)floorf(sy);
            const int   q1 = min(q0 + 1, ph - 1);
            const float wy = sy - (float)q0;
            sRowIdx[o][2 * a + 0] = q0;
            sRowIdx[o][2 * a + 1] = q1;
            sRowW[o][2 * a + 0] = W[a] * (1.0f - wy);
            sRowW[o][2 * a + 1] = W[a] * wy;
            if (o == 0  && a == 0) sRowLo = q0;
            if (o == 15 && a == 1) sRowHi = q1;
        }
    } else if (tid < 32) {
        const int o = tid - 16;
        const float sf = (float)(x2i - x1i);
        const float s  = fmaxf(((float)o + 0.5f) * sf / (float)OHW - 0.5f, 0.0f);
        const int   j0 = (int)floorf(s);
        const int   j1 = min(j0 + 1, (x2i - x1i) - 1);
        const float wt = s - (float)j0;
        const int xi[2]  = { x1i + j0, x1i + j1 };
        const float W[2] = { 1.0f - wt, wt };
        #pragma unroll
        for (int a = 0; a < 2; ++a) {
            sImgX[o][a]  = xi[a];
            sImgWX[o][a] = W[a];
            const float sx = fmaxf(((float)xi[a] + 0.5f) * scale - 0.5f, 0.0f);
            const int   q0 = (int)floorf(sx);
            const int   q1 = min(q0 + 1, ph - 1);
            const float wx = sx - (float)q0;
            sColIdx[o][2 * a + 0] = q0;
            sColIdx[o][2 * a + 1] = q1;
            sColW[o][2 * a + 0] = W[a] * (1.0f - wx);
            sColW[o][2 * a + 1] = W[a] * wx;
            if (o == 0  && a == 0) sColLo = q0;
            if (o == 15 && a == 1) sColHi = q1;
        }
    }
    __syncthreads();

    if (grp == 0) {
        // ---- 3 image channels: 4-tap bilinear on the full-res image ----
        const int   iy0 = sImgY[oy][0], iy1 = sImgY[oy][1];
        const int   ix0 = sImgX[ox][0], ix1 = sImgX[ox][1];
        const float wy0 = sImgWY[oy][0], wy1 = sImgWY[oy][1];
        const float wx0 = sImgWX[ox][0], wx1 = sImgWX[ox][1];
        const float* ib = imgs + (size_t)b * 3 * IHW * IHW;
        #pragma unroll
        for (int c = 0; c < 3; ++c) {
            const float* pc = ib + (size_t)c * IHW * IHW;
            const float v =
                wy0 * (wx0 * __ldg(pc + iy0 * IHW + ix0) + wx1 * __ldg(pc + iy0 * IHW + ix1)) +
                wy1 * (wx0 * __ldg(pc + iy1 * IHW + ix0) + wx1 * __ldg(pc + iy1 * IHW + ix1));
            outBox[c * NPIX + tid] = v;
        }
        return;
    }

    // ---- 16 feature channels: double-buffered window staging + smem gather ----
    const float* P = (lvl == 2) ? p2 : (lvl == 3) ? p3 : (lvl == 4) ? p4 : p5;
    const int hw = ph * ph;

    const int rowLo = sRowLo;
    const int colLo = sColLo;
    const int rowSpan = min(sRowHi - rowLo + 1, MAXSPAN);
    const int colSpan = min(sColHi - colLo + 1, MAXSPAN);

    // channel-invariant per-thread tap offsets + weights in registers
    int   rOff[4], cOff[4];
    float rW[4], cW[4];
    #pragma unroll
    for (int i = 0; i < 4; ++i) {
        rOff[i] = (sRowIdx[oy][i] - rowLo) * SSTRIDE;
        rW[i]   = sRowW[oy][i];
        cOff[i] = sColIdx[ox][i] - colLo;
        cW[i]   = sColW[ox][i];
    }

    const int cg0 = (grp - 1) * 16;
    const float* gwin = P + ((size_t)b * CC + cg0) * hw + rowLo * ph + colLo;
    float* outg = outBox + (size_t)(3 + cg0) * NPIX + tid;

    const int wid  = tid >> 5;
    const int lane = tid & 31;

    // warp-per-row, lane-per-col staging (no integer division, coalesced rows)
    auto stage = [&](int buf, int cb) {
        const float* gb = gwin + (size_t)cb * CHB * hw;
        for (int r = wid; r < rowSpan; r += 8) {
            const float* grow = gb + r * ph;
            float* s0 = &sWin[buf][0][r * SSTRIDE];
            float* s1 = &sWin[buf][1][r * SSTRIDE];
            for (int c = lane; c < colSpan; c += 32) {
                s0[c] = __ldg(grow + c);
                s1[c] = __ldg(grow + hw + c);
            }
        }
    };

    stage(0, 0);   // prologue

    #pragma unroll
    for (int cb = 0; cb < NBATCH; ++cb) {
        __syncthreads();                       // batch cb staged; batch cb-1 consumers done
        if (cb + 1 < NBATCH) stage((cb + 1) & 1, cb + 1);   // prefetch into idle buffer

        const int buf = cb & 1;
        #pragma unroll
        for (int ch = 0; ch < CHB; ++ch) {
            const float* sb = sWin[buf][ch];
            float acc = 0.0f;
            #pragma unroll
            for (int i = 0; i < 4; ++i) {
                const float* sr = sb + rOff[i];
                float part = cW[0] * sr[cOff[0]];
                part = fmaf(cW[1], sr[cOff[1]], part);
                part = fmaf(cW[2], sr[cOff[2]], part);
                part = fmaf(cW[3], sr[cOff[3]], part);
                acc = fmaf(rW[i], part, acc);
            }
            outg[(size_t)(cb * CHB + ch) * NPIX] = acc;
        }
    }
}

extern "C" void kernel_launch(void* const* d_in, const int* in_sizes, int n_in,
                              void* d_out, int out_size)
{
    const float* imgs    = (const float*)d_in[0];
    const float* bboxess = (const float*)d_in[1];
    const int*   counts  = (const int*)  d_in[2];
    const float* p2      = (const float*)d_in[3];
    const float* p3      = (const float*)d_in[4];
    const float* p4      = (const float*)d_in[5];
    const float* p5      = (const float*)d_in[6];

    dim3 grid(BB * KK, 17);
    roialign_kernel<<<grid, 256>>>(imgs, bboxess, counts, p2, p3, p4, p5,
                                   (float*)d_out);
}

// round 5
// speedup vs baseline: 1.2182x; 1.2182x over previous
#include <cuda_runtime.h>
#include <cuda_bf16.h>
#include <cstdint>

#define BB   2
#define KK   32
#define CC   256
#define IHW  512
#define OHW  16
#define NCH  (3 + CC)
#define NPIX (OHW * OHW)

#define MAXSPAN 40          // window span bound (analysis: <= ~36)
#define SSTRIDE 41          // odd stride -> conflict-free banks
#define CHB     2           // channels per staged batch
#define NBATCH  (16 / CHB)  // 8 batches per feature group

__device__ __forceinline__ void cp_async4(void* smem_dst, const void* gmem_src) {
    unsigned saddr = (unsigned)__cvta_generic_to_shared(smem_dst);
    asm volatile("cp.async.ca.shared.global [%0], [%1], 4;\n" :: "r"(saddr), "l"(gmem_src));
}
__device__ __forceinline__ void cp_async_commit() {
    asm volatile("cp.async.commit_group;\n" ::: "memory");
}
__device__ __forceinline__ void cp_async_wait_all() {
    asm volatile("cp.async.wait_group 0;\n" ::: "memory");
}

__global__ __launch_bounds__(256, 6)
void roialign_kernel(const float* __restrict__ imgs,
                     const float* __restrict__ bboxess,
                     const int*   __restrict__ counts,
                     const float* __restrict__ p2,
                     const float* __restrict__ p3,
                     const float* __restrict__ p4,
                     const float* __restrict__ p5,
                     float*       __restrict__ out)
{
    const int bk  = blockIdx.x;          // 0..B*K-1
    const int b   = bk / KK;
    const int k   = bk % KK;
    const int grp = blockIdx.y;          // 0 = image channels, 1..16 = feature groups
    const int tid = threadIdx.x;         // one output pixel
    const int oy  = tid >> 4;
    const int ox  = tid & 15;

    float* outBox = out + (size_t)bk * NCH * NPIX;

    const bool valid = (k < __ldg(counts + b));
    if (!valid) {
        if (grp == 0) {
            #pragma unroll
            for (int c = 0; c < 3; ++c) outBox[c * NPIX + tid] = 0.0f;
        } else {
            const int c0 = 3 + (grp - 1) * 16;
            #pragma unroll
            for (int cc = 0; cc < 16; ++cc) outBox[(c0 + cc) * NPIX + tid] = 0.0f;
        }
        return;
    }

    // ---- per-box scalars ----
    const float by1 = __ldg(bboxess + bk * 4 + 0);
    const float bx1 = __ldg(bboxess + bk * 4 + 1);
    const float by2 = __ldg(bboxess + bk * 4 + 2);
    const float bx2 = __ldg(bboxess + bk * 4 + 3);

    const float area = (by2 - by1) * (bx2 - bx1);
    float lx = 6.0f + 0.5f * log2f(area * (1.0f / ((float)IHW * (float)IHW)));
    lx = fminf(fmaxf(lx, 2.0f), 5.0f);
    const int lvl = (int)rintf(lx);
    const int ph  = IHW >> lvl;
    const float scale = (float)ph / (float)IHW;

    int y1i = min(max((int)rintf(by1), 0), IHW - 1);
    int x1i = min(max((int)rintf(bx1), 0), IHW - 1);
    int y2i = min(max((int)rintf(by2), y1i + 1), IHW);
    int x2i = min(max((int)rintf(bx2), x1i + 1), IHW);

    // ---- tap tables ----
    __shared__ int   sRowIdx[OHW][4];
    __shared__ float sRowW[OHW][4];
    __shared__ int   sColIdx[OHW][4];
    __shared__ float sColW[OHW][4];
    __shared__ int   sImgY[OHW][2];
    __shared__ float sImgWY[OHW][2];
    __shared__ int   sImgX[OHW][2];
    __shared__ float sImgWX[OHW][2];
    __shared__ int   sRowLo, sRowHi, sColLo, sColHi;
    __shared__ float sWin[2][CHB][MAXSPAN * SSTRIDE];   // ping-pong, 26.2 KB

    if (tid < 16) {
        const int o = tid;
        const float sf = (float)(y2i - y1i);
        const float s  = fmaxf(((float)o + 0.5f) * sf / (float)OHW - 0.5f, 0.0f);
        const int   j0 = (int)floorf(s);
        const int   j1 = min(j0 + 1, (y2i - y1i) - 1);
        const float wt = s - (float)j0;
        const int yi[2]  = { y1i + j0, y1i + j1 };
        const float W[2] = { 1.0f - wt, wt };
        #pragma unroll
        for (int a = 0; a < 2; ++a) {
            sImgY[o][a]  = yi[a];
            sImgWY[o][a] = W[a];
            const float sy = fmaxf(((float)yi[a] + 0.5f) * scale - 0.5f, 0.0f);
            const int   q0 = (int)floorf(sy);
            const int   q1 = min(q0 + 1, ph - 1);
            const float wy = sy - (float)q0;
            sRowIdx[o][2 * a + 0] = q0;
            sRowIdx[o][2 * a + 1] = q1;
            sRowW[o][2 * a + 0] = W[a] * (1.0f - wy);
            sRowW[o][2 * a + 1] = W[a] * wy;
            if (o == 0  && a == 0) sRowLo = q0;
            if (o == 15 && a == 1) sRowHi = q1;
        }
    } else if (tid < 32) {
        const int o = tid - 16;
        const float sf = (float)(x2i - x1i);
        const float s  = fmaxf(((float)o + 0.5f) * sf / (float)OHW - 0.5f, 0.0f);
        const int   j0 = (int)floorf(s);
        const int   j1 = min(j0 + 1, (x2i - x1i) - 1);
        const float wt = s - (float)j0;
        const int xi[2]  = { x1i + j0, x1i + j1 };
        const float W[2] = { 1.0f - wt, wt };
        #pragma unroll
        for (int a = 0; a < 2; ++a) {
            sImgX[o][a]  = xi[a];
            sImgWX[o][a] = W[a];
            const float sx = fmaxf(((float)xi[a] + 0.5f) * scale - 0.5f, 0.0f);
            const int   q0 = (int)floorf(sx);
            const int   q1 = min(q0 + 1, ph - 1);
            const float wx = sx - (float)q0;
            sColIdx[o][2 * a + 0] = q0;
            sColIdx[o][2 * a + 1] = q1;
            sColW[o][2 * a + 0] = W[a] * (1.0f - wx);
            sColW[o][2 * a + 1] = W[a] * wx;
            if (o == 0  && a == 0) sColLo = q0;
            if (o == 15 && a == 1) sColHi = q1;
        }
    }
    __syncthreads();

    if (grp == 0) {
        // ---- 3 image channels: 4-tap bilinear on the full-res image ----
        const int   iy0 = sImgY[oy][0], iy1 = sImgY[oy][1];
        const int   ix0 = sImgX[ox][0], ix1 = sImgX[ox][1];
        const float wy0 = sImgWY[oy][0], wy1 = sImgWY[oy][1];
        const float wx0 = sImgWX[ox][0], wx1 = sImgWX[ox][1];
        const float* ib = imgs + (size_t)b * 3 * IHW * IHW;
        #pragma unroll
        for (int c = 0; c < 3; ++c) {
            const float* pc = ib + (size_t)c * IHW * IHW;
            const float v =
                wy0 * (wx0 * __ldg(pc + iy0 * IHW + ix0) + wx1 * __ldg(pc + iy0 * IHW + ix1)) +
                wy1 * (wx0 * __ldg(pc + iy1 * IHW + ix0) + wx1 * __ldg(pc + iy1 * IHW + ix1));
            outBox[c * NPIX + tid] = v;
        }
        return;
    }

    // ---- 16 feature channels: cp.async double-buffered staging + smem gather ----
    const float* P = (lvl == 2) ? p2 : (lvl == 3) ? p3 : (lvl == 4) ? p4 : p5;
    const int hw = ph * ph;

    const int rowLo = sRowLo;
    const int colLo = sColLo;
    const int rowSpan = min(sRowHi - rowLo + 1, MAXSPAN);
    const int colSpan = min(sColHi - colLo + 1, MAXSPAN);

    // channel-invariant per-thread tap offsets + weights in registers
    int   rOff[4], cOff[4];
    float rW[4], cW[4];
    #pragma unroll
    for (int i = 0; i < 4; ++i) {
        rOff[i] = (sRowIdx[oy][i] - rowLo) * SSTRIDE;
        rW[i]   = sRowW[oy][i];
        cOff[i] = sColIdx[ox][i] - colLo;
        cW[i]   = sColW[ox][i];
    }

    const int cg0 = (grp - 1) * 16;
    const float* gwin = P + ((size_t)b * CC + cg0) * hw + rowLo * ph + colLo;
    float* outg = outBox + (size_t)(3 + cg0) * NPIX + tid;

    const int wid  = tid >> 5;
    const int lane = tid & 31;

    // warp-per-row, lane-per-col async staging (no registers involved)
    auto stage_async = [&](int buf, int cb) {
        const float* gb = gwin + (size_t)cb * CHB * hw;
        for (int r = wid; r < rowSpan; r += 8) {
            const float* grow = gb + r * ph;
            float* s0 = &sWin[buf][0][r * SSTRIDE];
            float* s1 = &sWin[buf][1][r * SSTRIDE];
            for (int c = lane; c < colSpan; c += 32) {
                cp_async4(s0 + c, grow + c);
                cp_async4(s1 + c, grow + hw + c);
            }
        }
        cp_async_commit();
    };

    // prologue: stage batch 0 and make it visible
    stage_async(0, 0);
    cp_async_wait_all();
    __syncthreads();

    #pragma unroll
    for (int cb = 0; cb < NBATCH; ++cb) {
        // issue async staging for next batch (no register deps -> compute proceeds)
        if (cb + 1 < NBATCH) stage_async((cb + 1) & 1, cb + 1);

        const int buf = cb & 1;
        #pragma unroll
        for (int ch = 0; ch < CHB; ++ch) {
            const float* sb = sWin[buf][ch];
            float acc = 0.0f;
            #pragma unroll
            for (int i = 0; i < 4; ++i) {
                const float* sr = sb + rOff[i];
                float part = cW[0] * sr[cOff[0]];
                part = fmaf(cW[1], sr[cOff[1]], part);
                part = fmaf(cW[2], sr[cOff[2]], part);
                part = fmaf(cW[3], sr[cOff[3]], part);
                acc = fmaf(rW[i], part, acc);
            }
            outg[(size_t)(cb * CHB + ch) * NPIX] = acc;
        }

        if (cb + 1 < NBATCH) {
            cp_async_wait_all();      // claim next batch's copies (this thread)
            __syncthreads();          // make them visible block-wide; also fences buf reuse
        }
    }
}

extern "C" void kernel_launch(void* const* d_in, const int* in_sizes, int n_in,
                              void* d_out, int out_size)
{
    const float* imgs    = (const float*)d_in[0];
    const float* bboxess = (const float*)d_in[1];
    const int*   counts  = (const int*)  d_in[2];
    const float* p2      = (const float*)d_in[3];
    const float* p3      = (const float*)d_in[4];
    const float* p4      = (const float*)d_in[5];
    const float* p5      = (const float*)d_in[6];

    dim3 grid(BB * KK, 17);
    roialign_kernel<<<grid, 256>>>(imgs, bboxess, counts, p2, p3, p4, p5,
                                   (float*)d_out);
}

// round 6
// speedup vs baseline: 1.7516x; 1.4379x over previous
#include <cuda_runtime.h>
#include <cuda_bf16.h>
#include <cstdint>

#define BB   2
#define KK   32
#define CC   256
#define IHW  512
#define OHW  16
#define NCH  (3 + CC)
#define NPIX (OHW * OHW)

#define MAXSPAN 40          // window span bound (analysis: <= ~38 incl. clamp extension)
#define SSTRIDE 41          // odd stride -> conflict-free banks
#define TSTRIDE 17          // tmp row stride (16 ox + 1 pad)
#define CHB     4           // channels per staged batch
#define NBATCH  (16 / CHB)

__global__ __launch_bounds__(256, 5)
void roialign_kernel(const float* __restrict__ imgs,
                     const float* __restrict__ bboxess,
                     const int*   __restrict__ counts,
                     const float* __restrict__ p2,
                     const float* __restrict__ p3,
                     const float* __restrict__ p4,
                     const float* __restrict__ p5,
                     float*       __restrict__ out)
{
    const int bk  = blockIdx.x;          // 0..B*K-1
    const int b   = bk / KK;
    const int k   = bk % KK;
    const int grp = blockIdx.y;          // 0 = image channels, 1..16 = feature groups
    const int tid = threadIdx.x;
    const int oy  = tid >> 4;
    const int ox  = tid & 15;

    float* outBox = out + (size_t)bk * NCH * NPIX;

    const bool valid = (k < __ldg(counts + b));
    if (!valid) {
        if (grp == 0) {
            #pragma unroll
            for (int c = 0; c < 3; ++c) outBox[c * NPIX + tid] = 0.0f;
        } else {
            const int c0 = 3 + (grp - 1) * 16;
            #pragma unroll
            for (int cc = 0; cc < 16; ++cc) outBox[(c0 + cc) * NPIX + tid] = 0.0f;
        }
        return;
    }

    // ---- per-box scalars ----
    const float by1 = __ldg(bboxess + bk * 4 + 0);
    const float bx1 = __ldg(bboxess + bk * 4 + 1);
    const float by2 = __ldg(bboxess + bk * 4 + 2);
    const float bx2 = __ldg(bboxess + bk * 4 + 3);

    const float area = (by2 - by1) * (bx2 - bx1);
    float lx = 6.0f + 0.5f * log2f(area * (1.0f / ((float)IHW * (float)IHW)));
    lx = fminf(fmaxf(lx, 2.0f), 5.0f);
    const int lvl = (int)rintf(lx);
    const int ph  = IHW >> lvl;
    const float scale = (float)ph / (float)IHW;

    int y1i = min(max((int)rintf(by1), 0), IHW - 1);
    int x1i = min(max((int)rintf(bx1), 0), IHW - 1);
    int y2i = min(max((int)rintf(by2), y1i + 1), IHW);
    int x2i = min(max((int)rintf(bx2), x1i + 1), IHW);

    // ---- tap tables ----
    __shared__ int   sRowIdx[OHW][4];    // global feature row per (oy, tap)
    __shared__ float sRowW[OHW][4];
    __shared__ int   sCb[OHW][2];        // per-ox column pair base (global), clamp-safe
    __shared__ float sWlo[OHW][2];
    __shared__ float sWhi[OHW][2];
    __shared__ int   sImgY[OHW][2];
    __shared__ float sImgWY[OHW][2];
    __shared__ int   sImgX[OHW][2];
    __shared__ float sImgWX[OHW][2];
    __shared__ int   sRowLo, sRowHi, sColLo, sColHi;
    __shared__ float sWin[CHB][MAXSPAN * SSTRIDE];   // 26.24 KB raw windows
    __shared__ float sTmp[CHB][MAXSPAN * TSTRIDE];   // 10.88 KB column partials

    if (tid < 16) {
        const int o = tid;
        const float sf = (float)(y2i - y1i);
        const float s  = fmaxf(((float)o + 0.5f) * sf / (float)OHW - 0.5f, 0.0f);
        const int   j0 = (int)floorf(s);
        const int   j1 = min(j0 + 1, (y2i - y1i) - 1);
        const float wt = s - (float)j0;
        const int yi[2]  = { y1i + j0, y1i + j1 };
        const float W[2] = { 1.0f - wt, wt };
        #pragma unroll
        for (int a = 0; a < 2; ++a) {
            sImgY[o][a]  = yi[a];
            sImgWY[o][a] = W[a];
            const float sy = fmaxf(((float)yi[a] + 0.5f) * scale - 0.5f, 0.0f);
            const int   q0 = (int)floorf(sy);
            const int   q1 = min(q0 + 1, ph - 1);
            const float wy = sy - (float)q0;
            sRowIdx[o][2 * a + 0] = q0;
            sRowIdx[o][2 * a + 1] = q1;
            sRowW[o][2 * a + 0] = W[a] * (1.0f - wy);
            sRowW[o][2 * a + 1] = W[a] * wy;
            if (o == 0  && a == 0) sRowLo = q0;
            if (o == 15 && a == 1) sRowHi = q1;
        }
    } else if (tid < 32) {
        const int o = tid - 16;
        const float sf = (float)(x2i - x1i);
        const float s  = fmaxf(((float)o + 0.5f) * sf / (float)OHW - 0.5f, 0.0f);
        const int   j0 = (int)floorf(s);
        const int   j1 = min(j0 + 1, (x2i - x1i) - 1);
        const float wt = s - (float)j0;
        const int xi[2]  = { x1i + j0, x1i + j1 };
        const float W[2] = { 1.0f - wt, wt };
        #pragma unroll
        for (int a = 0; a < 2; ++a) {
            sImgX[o][a]  = xi[a];
            sImgWX[o][a] = W[a];
            const float sx = fmaxf(((float)xi[a] + 0.5f) * scale - 0.5f, 0.0f);
            const int   q0 = (int)floorf(sx);
            const int   q1 = min(q0 + 1, ph - 1);
            const float wx = sx - (float)q0;
            // clamp-safe adjacent pair: value = wlo*win[cb] + whi*win[cb+1]
            int   cb;
            float wlo, whi;
            if (q1 > q0) { cb = q0;     wlo = W[a] * (1.0f - wx); whi = W[a] * wx; }
            else         { cb = q0 - 1; wlo = 0.0f;               whi = W[a]; }
            sCb[o][a]  = cb;
            sWlo[o][a] = wlo;
            sWhi[o][a] = whi;
            if (o == 0  && a == 0) sColLo = cb;
            if (o == 15 && a == 1) sColHi = cb + 1;
        }
    }
    __syncthreads();

    if (grp == 0) {
        // ---- 3 image channels: 4-tap bilinear on the full-res image ----
        const int   iy0 = sImgY[oy][0], iy1 = sImgY[oy][1];
        const int   ix0 = sImgX[ox][0], ix1 = sImgX[ox][1];
        const float wy0 = sImgWY[oy][0], wy1 = sImgWY[oy][1];
        const float wx0 = sImgWX[ox][0], wx1 = sImgWX[ox][1];
        const float* ib = imgs + (size_t)b * 3 * IHW * IHW;
        #pragma unroll
        for (int c = 0; c < 3; ++c) {
            const float* pc = ib + (size_t)c * IHW * IHW;
            const float v =
                wy0 * (wx0 * __ldg(pc + iy0 * IHW + ix0) + wx1 * __ldg(pc + iy0 * IHW + ix1)) +
                wy1 * (wx0 * __ldg(pc + iy1 * IHW + ix0) + wx1 * __ldg(pc + iy1 * IHW + ix1));
            outBox[c * NPIX + tid] = v;
        }
        return;
    }

    // ---- 16 feature channels: staged window + separable two-stage contraction ----
    const float* P = (lvl == 2) ? p2 : (lvl == 3) ? p3 : (lvl == 4) ? p4 : p5;
    const int hw = ph * ph;

    const int rowLo = sRowLo;
    const int colLo = sColLo;
    const int rowSpan = min(sRowHi - rowLo + 1, MAXSPAN);
    const int colSpan = min(sColHi - colLo + 1, MAXSPAN);
    const int nWin = rowSpan * colSpan;

    // per-thread stage2 row taps (oy-indexed)
    int   rRel[4];
    float rW[4];
    #pragma unroll
    for (int i = 0; i < 4; ++i) {
        rRel[i] = (sRowIdx[oy][i] - rowLo) * TSTRIDE + ox;
        rW[i]   = sRowW[oy][i];
    }
    // per-thread stage1 column pairs (ox-indexed; ox == stage1 ox by construction)
    const int   cb0 = sCb[ox][0] - colLo, cb1 = sCb[ox][1] - colLo;
    const float wlo0 = sWlo[ox][0], whi0 = sWhi[ox][0];
    const float wlo1 = sWlo[ox][1], whi1 = sWhi[ox][1];

    // stage1 thread mapping: ch = tid>>6, rowgroup = (tid>>4)&3, ox = tid&15
    const int s1ch = tid >> 6;
    const int s1rg = (tid >> 4) & 3;

    const int cg0 = (grp - 1) * 16;
    const float* gwin = P + ((size_t)b * CC + cg0) * hw + rowLo * ph + colLo;
    float* outg = outBox + (size_t)(3 + cg0) * NPIX + tid;

    for (int cb = 0; cb < NBATCH; ++cb) {
        const float* gb = gwin + (size_t)cb * CHB * hw;

        // --- raw window staging (coalesced) ---
        for (int idx = tid; idx < nWin; idx += 256) {
            const int r = idx / colSpan;
            const int c = idx - r * colSpan;
            const int g = r * ph + c;
            const int s = r * SSTRIDE + c;
            #pragma unroll
            for (int ch = 0; ch < CHB; ++ch)
                sWin[ch][s] = __ldg(gb + (size_t)ch * hw + g);
        }
        __syncthreads();

        // --- stage1: column contraction -> sTmp[ch][r][ox] ---
        {
            const float* wb = sWin[s1ch];
            float* tb = sTmp[s1ch];
            for (int r = s1rg; r < rowSpan; r += 4) {
                const float* wr = wb + r * SSTRIDE;
                float v = wlo0 * wr[cb0];
                v = fmaf(whi0, wr[cb0 + 1], v);
                v = fmaf(wlo1, wr[cb1], v);
                v = fmaf(whi1, wr[cb1 + 1], v);
                tb[r * TSTRIDE + ox] = v;
            }
        }
        __syncthreads();

        // --- stage2: row contraction -> output ---
        #pragma unroll
        for (int ch = 0; ch < CHB; ++ch) {
            const float* tb = sTmp[ch];
            float acc = rW[0] * tb[rRel[0]];
            acc = fmaf(rW[1], tb[rRel[1]], acc);
            acc = fmaf(rW[2], tb[rRel[2]], acc);
            acc = fmaf(rW[3], tb[rRel[3]], acc);
            outg[(size_t)(cb * CHB + ch) * NPIX] = acc;
        }
        __syncthreads();   // before next batch overwrites sWin/sTmp
    }
}

extern "C" void kernel_launch(void* const* d_in, const int* in_sizes, int n_in,
                              void* d_out, int out_size)
{
    const float* imgs    = (const float*)d_in[0];
    const float* bboxess = (const float*)d_in[1];
    const int*   counts  = (const int*)  d_in[2];
    const float* p2      = (const float*)d_in[3];
    const float* p3      = (const float*)d_in[4];
    const float* p4      = (const float*)d_in[5];
    const float* p5      = (const float*)d_in[6];

    dim3 grid(BB * KK, 17);
    roialign_kernel<<<grid, 256>>>(imgs, bboxess, counts, p2, p3, p4, p5,
                                   (float*)d_out);
}